// round 13
// baseline (speedup 1.0000x reference)
#include <cuda_runtime.h>
#include <cuda_bf16.h>
#include <math_constants.h>

#define B_  2
#define S_  2048
#define D_  1024
#define H_  16
#define HD_ 64
#define NT_ 32   // S_/64 attn k-tiles
#define KT_ 64   // D_/16 qkv k-tiles
#define L2E 1.4426950408889634f

__device__ float g_Q[B_ * H_ * S_ * HD_];
// attention packed operands (written directly by qkv epilogue)
__device__ uint4  g_Kp[B_ * H_ * NT_ * 16 * 64];
__device__ float4 g_Vp[B_ * H_ * NT_ * 16 * 64];
// qkv packed inputs
__device__ uint4  g_Xp[KT_ * 256 * 2 * 32];
__device__ uint4  g_Wp[3 * KT_ * 1024 * 4];

__device__ __forceinline__ unsigned f2tf(float x) {
    unsigned r;
    asm("cvt.rna.tf32.f32 %0, %1;" : "=r"(r) : "f"(x));
    return r;
}
__device__ __forceinline__ float tf2f(unsigned u) { return __uint_as_float(u); }
__device__ __forceinline__ float tfr(float x) { return tf2f(f2tf(x)); }
__device__ __forceinline__ float bfhi(float x) {
    return __bfloat162float(__float2bfloat16_rn(x));
}
__device__ __forceinline__ unsigned packbf(float a, float b) {
    __nv_bfloat162 h = __floats2bfloat162_rn(a, b);
    return *(unsigned*)&h;
}
__device__ __forceinline__ float ex2f(float x) {
    float r;
    asm("ex2.approx.ftz.f32 %0, %1;" : "=f"(r) : "f"(x));
    return r;
}
__device__ __forceinline__ void mma8(float c[4], const unsigned a[4],
                                     unsigned b0, unsigned b1) {
    asm volatile(
        "mma.sync.aligned.m16n8k8.row.col.f32.tf32.tf32.f32 "
        "{%0,%1,%2,%3},{%4,%5,%6,%7},{%8,%9},{%0,%1,%2,%3};"
        : "+f"(c[0]), "+f"(c[1]), "+f"(c[2]), "+f"(c[3])
        : "r"(a[0]), "r"(a[1]), "r"(a[2]), "r"(a[3]), "r"(b0), "r"(b1));
}
__device__ __forceinline__ void mma16(float c[4], const unsigned a[4],
                                      unsigned b0, unsigned b1) {
    asm volatile(
        "mma.sync.aligned.m16n8k16.row.col.f32.bf16.bf16.f32 "
        "{%0,%1,%2,%3},{%4,%5,%6,%7},{%8,%9},{%0,%1,%2,%3};"
        : "+f"(c[0]), "+f"(c[1]), "+f"(c[2]), "+f"(c[3])
        : "r"(a[0]), "r"(a[1]), "r"(a[2]), "r"(a[3]), "r"(b0), "r"(b1));
}
__device__ __forceinline__ void cpa16(unsigned dst, const void* src) {
    asm volatile("cp.async.cg.shared.global [%0], [%1], 16;" :: "r"(dst), "l"(src));
}

// ---------------------------------------------------------------------------
// pack_in: X -> a-frags (blocks [0, 2048)), W -> b-frags (blocks [2048, 5120))
// ---------------------------------------------------------------------------
__global__ __launch_bounds__(256) void pack_in_kernel(
    const float* __restrict__ X,
    const float* __restrict__ Wq, const float* __restrict__ Wk, const float* __restrict__ Wv)
{
    if (blockIdx.x < 2048) {
        const int id = blockIdx.x * 256 + threadIdx.x;
        const int lane = id & 31;
        const int t = lane & 3, g = lane >> 2;
        const int mG = (id >> 5) & 255;
        const int kt = id >> 13;
        const int m  = mG * 16 + g;
        const int c0 = kt * 16 + 2 * t;

        float2 x00 = *(const float2*)&X[(size_t)m * D_ + c0];
        float2 x01 = *(const float2*)&X[(size_t)m * D_ + c0 + 8];
        float2 x10 = *(const float2*)&X[(size_t)(m + 8) * D_ + c0];
        float2 x11 = *(const float2*)&X[(size_t)(m + 8) * D_ + c0 + 8];

        float h00 = bfhi(x00.x), h01 = bfhi(x00.y);
        float h10 = bfhi(x10.x), h11 = bfhi(x10.y);
        float h02 = bfhi(x01.x), h03 = bfhi(x01.y);
        float h12 = bfhi(x11.x), h13 = bfhi(x11.y);

        uint4 hi, lo;
        hi.x = packbf(h00, h01);             hi.y = packbf(h10, h11);
        hi.z = packbf(h02, h03);             hi.w = packbf(h12, h13);
        lo.x = packbf(x00.x - h00, x00.y - h01);
        lo.y = packbf(x10.x - h10, x10.y - h11);
        lo.z = packbf(x01.x - h02, x01.y - h03);
        lo.w = packbf(x11.x - h12, x11.y - h13);

        const size_t base = ((size_t)kt * 256 + mG) * 64;
        g_Xp[base + lane]      = hi;
        g_Xp[base + 32 + lane] = lo;
    } else {
        const int id = (blockIdx.x - 2048) * 256 + threadIdx.x;
        const int t  = id & 3;
        const int n  = (id >> 2) & 1023;
        const int kt = (id >> 12) & 63;
        const int z  = id >> 18;
        const float* W = (z == 0) ? Wq : (z == 1) ? Wk : Wv;
        const int k0 = kt * 16;

        float w0 = W[(size_t)(k0 + 2*t    ) * D_ + n];
        float w1 = W[(size_t)(k0 + 2*t + 1) * D_ + n];
        float w2 = W[(size_t)(k0 + 2*t + 8) * D_ + n];
        float w3 = W[(size_t)(k0 + 2*t + 9) * D_ + n];
        float h0 = bfhi(w0), h1 = bfhi(w1), h2 = bfhi(w2), h3 = bfhi(w3);

        uint4 frag;
        frag.x = packbf(h0, h1);
        frag.y = packbf(h2, h3);
        frag.z = packbf(w0 - h0, w1 - h1);
        frag.w = packbf(w2 - h2, w3 - h3);
        g_Wp[id] = frag;
    }
}

// ---------------------------------------------------------------------------
// QKV projection: 4-stage cp.async pipeline (64KB), pure-copy mainloop.
// Q is scaled by 0.125*log2e (scores land in log2 domain for ex2 softmax).
// ---------------------------------------------------------------------------
#define QSTAGES 4
__global__ __launch_bounds__(256) void qkv_kernel(
    const float* __restrict__ bq, const float* __restrict__ bk, const float* __restrict__ bv)
{
    const int z = blockIdx.z;
    const float* bias = (z == 0) ? bq : (z == 1) ? bk : bv;

    extern __shared__ uint4 sm[];     // QSTAGES x 1024 uint4 (16KB each)
    unsigned sm_base;
    {
        void* p = sm;
        asm("{ .reg .u64 tmp; cvta.to.shared.u64 tmp, %1; cvt.u32.u64 %0, tmp; }"
            : "=r"(sm_base) : "l"(p));
    }

    const int tid  = threadIdx.x;
    const int lane = tid & 31;
    const int warp = tid >> 5;
    const int wm = warp & 3;
    const int wn = warp >> 2;
    const int rowBase = blockIdx.y * 128;
    const int colBase = blockIdx.x * 128;
    const int g = lane >> 2;
    const int t = lane & 3;

    const uint4* gX = g_Xp + (size_t)(rowBase >> 4) * 64;
    const uint4* gW = g_Wp + (size_t)z * (KT_ * 4096) + colBase * 4;

    float acc[2][8][4];
    #pragma unroll
    for (int mt = 0; mt < 2; mt++)
        #pragma unroll
        for (int nt = 0; nt < 8; nt++)
            #pragma unroll
            for (int i = 0; i < 4; i++) acc[mt][nt][i] = 0.0f;

    // prologue: tiles 0..2 into stages 0..2 (one commit each)
    #pragma unroll
    for (int st = 0; st < QSTAGES - 1; st++) {
        const unsigned dst = sm_base + st * 16384;
        #pragma unroll
        for (int i = 0; i < 4; i++) {
            const int j = i * 256 + tid;
            if (j < 512) cpa16(dst + j * 16, gX + (size_t)st * 16384 + j);
            else         cpa16(dst + j * 16, gW + (size_t)st * 4096 + (j - 512));
        }
        asm volatile("cp.async.commit_group;");
    }

    for (int kt = 0; kt < KT_; kt++) {
        if (kt + QSTAGES - 1 < KT_) {
            const int st = (kt + QSTAGES - 1) & (QSTAGES - 1);
            const unsigned dst = sm_base + st * 16384;
            const size_t xo = (size_t)(kt + QSTAGES - 1) * 16384;
            const size_t wo = (size_t)(kt + QSTAGES - 1) * 4096;
            #pragma unroll
            for (int i = 0; i < 4; i++) {
                const int j = i * 256 + tid;
                if (j < 512) cpa16(dst + j * 16, gX + xo + j);
                else         cpa16(dst + j * 16, gW + wo + (j - 512));
            }
        }
        asm volatile("cp.async.commit_group;");
        asm volatile("cp.async.wait_group %0;" :: "n"(QSTAGES - 1));
        __syncthreads();

        const uint4* As = sm + (kt & (QSTAGES - 1)) * 1024;
        const uint4* Bs = As + 512;

        unsigned ah[2][4], al[2][4];
        #pragma unroll
        for (int mt = 0; mt < 2; mt++) {
            uint4 h4 = As[(wm * 2 + mt) * 64 + lane];
            uint4 l4 = As[(wm * 2 + mt) * 64 + 32 + lane];
            ah[mt][0] = h4.x; ah[mt][1] = h4.y; ah[mt][2] = h4.z; ah[mt][3] = h4.w;
            al[mt][0] = l4.x; al[mt][1] = l4.y; al[mt][2] = l4.z; al[mt][3] = l4.w;
        }
        #pragma unroll
        for (int nt = 0; nt < 8; nt++) {
            uint4 bb = Bs[(wn * 64 + nt * 8 + g) * 4 + t];
            #pragma unroll
            for (int mt = 0; mt < 2; mt++) {
                mma16(acc[mt][nt], ah[mt], bb.x, bb.y);
                mma16(acc[mt][nt], ah[mt], bb.z, bb.w);
                mma16(acc[mt][nt], al[mt], bb.x, bb.y);
            }
        }
        __syncthreads();
    }

    const int hh = blockIdx.x * 2 + wn;   // head index for this warp's n-range

    if (z == 0) {
        // ---- Q: bias, scale (0.125*log2e), STG.64 pairs to [B,H,S,HD] ----
        const float QSCALE = 0.125f * L2E;
        #pragma unroll
        for (int mt = 0; mt < 2; mt++) {
            #pragma unroll
            for (int nt = 0; nt < 8; nt++) {
                const int n0 = colBase + wn * 64 + nt * 8 + 2 * t;
                const float b0f = bias[n0], b1f = bias[n0 + 1];
                const int d = n0 & (HD_ - 1);
                #pragma unroll
                for (int half = 0; half < 2; half++) {
                    const int m = rowBase + wm * 32 + mt * 16 + g + half * 8;
                    const int b = m >> 11;
                    const int s = m & (S_ - 1);
                    float2 v;
                    v.x = (acc[mt][nt][2 * half]     + b0f) * QSCALE;
                    v.y = (acc[mt][nt][2 * half + 1] + b1f) * QSCALE;
                    *(float2*)&g_Q[(((size_t)(b * H_ + hh) * S_) + s) * HD_ + d] = v;
                }
            }
        }
    } else if (z == 1) {
        // ---- K: direct-pack bf16 hi/lo uint4 frags, coalesced ----
        #pragma unroll
        for (int mt = 0; mt < 2; mt++) {
            const int m0 = rowBase + wm * 32 + mt * 16 + g;
            const int b0 = m0 >> 11;
            const int s0 = m0 & (S_ - 1);
            const int ktt = s0 >> 6, r64 = s0 & 63;
            const size_t base = (size_t)((b0 * H_ + hh) * NT_ + ktt) * 1024;
            #pragma unroll
            for (int j = 0; j < 4; j++) {
                const int n0 = colBase + wn * 64 + 16 * j + 2 * t;
                const float b00 = bias[n0],     b01 = bias[n0 + 1];
                const float b08 = bias[n0 + 8], b09 = bias[n0 + 9];
                float a0 = acc[mt][2*j][0] + b00, a1 = acc[mt][2*j][1] + b01;
                float a2 = acc[mt][2*j+1][0] + b08, a3 = acc[mt][2*j+1][1] + b09;
                float h0 = bfhi(a0), h1 = bfhi(a1), h2 = bfhi(a2), h3 = bfhi(a3);
                uint4 fr;
                fr.x = packbf(h0, h1);        fr.y = packbf(h2, h3);
                fr.z = packbf(a0 - h0, a1 - h1);
                fr.w = packbf(a2 - h2, a3 - h3);
                g_Kp[base + (size_t)(j * 4 + t) * 64 + r64] = fr;
                a0 = acc[mt][2*j][2] + b00; a1 = acc[mt][2*j][3] + b01;
                a2 = acc[mt][2*j+1][2] + b08; a3 = acc[mt][2*j+1][3] + b09;
                h0 = bfhi(a0); h1 = bfhi(a1); h2 = bfhi(a2); h3 = bfhi(a3);
                fr.x = packbf(h0, h1);        fr.y = packbf(h2, h3);
                fr.z = packbf(a0 - h0, a1 - h1);
                fr.w = packbf(a2 - h2, a3 - h3);
                g_Kp[base + (size_t)(j * 4 + t) * 64 + r64 + 8] = fr;
            }
        }
    } else {
        // ---- V: direct-pack transposed tf32 float4 frags via pair shuffles ----
        #pragma unroll
        for (int mt = 0; mt < 2; mt++) {
            const int m0 = rowBase + wm * 32 + mt * 16 + g;
            const int b0 = m0 >> 11;
            const int s0 = m0 & (S_ - 1);
            const int ktt = s0 >> 6;
            const int kk2 = (s0 >> 4) & 3;
            const int tpp = g & 3;
            const int gh  = g >> 2;
            const size_t base = ((size_t)((b0 * H_ + hh) * NT_ + ktt) * 16
                                 + kk2 * 4 + tpp) * 64;
            #pragma unroll
            for (int nt = 0; nt < 8; nt++) {
                const int n0 = colBase + wn * 64 + nt * 8 + 2 * t;
                const float bb0 = bias[n0], bb1 = bias[n0 + 1];
                float v0 = acc[mt][nt][0] + bb0;
                float v1 = acc[mt][nt][1] + bb1;
                float v2 = acc[mt][nt][2] + bb0;
                float v3 = acc[mt][nt][3] + bb1;
                float x0 = __shfl_xor_sync(0xffffffffu, v0, 16);
                float x1 = __shfl_xor_sync(0xffffffffu, v1, 16);
                float x2 = __shfl_xor_sync(0xffffffffu, v2, 16);
                float x3 = __shfl_xor_sync(0xffffffffu, v3, 16);
                float4 fr; int d;
                if (gh == 0) {
                    d = nt * 8 + 2 * t;
                    fr.x = tfr(v0); fr.y = tfr(x0); fr.z = tfr(v2); fr.w = tfr(x2);
                } else {
                    d = nt * 8 + 2 * t + 1;
                    fr.x = tfr(x1); fr.y = tfr(v1); fr.z = tfr(x3); fr.w = tfr(v3);
                }
                g_Vp[base + d] = fr;
            }
        }
    }
}

// ---------------------------------------------------------------------------
// Flash attention: log2-domain ex2 softmax, mask added post-mma, P fed to
// tf32 mma as raw f32 (HW truncates). 64-query blocks, 128 threads / 4 warps.
// ---------------------------------------------------------------------------
#define KSLD 66
#define VSLD 66
#define KBUF_BYTES (16 * KSLD * 16)
#define VBUF_BYTES (16 * VSLD * 16)
__global__ __launch_bounds__(128) void attn_kernel(
    const float* __restrict__ mask, float* __restrict__ out)
{
    extern __shared__ char smc[];
    uint4*  Ks   = (uint4*)smc;
    float4* Vs   = (float4*)(smc + 2 * KBUF_BYTES);
    float*  msk  = (float*)(smc + 2 * KBUF_BYTES + 2 * VBUF_BYTES);
    float*  Qst  = (float*)(smc + 2 * KBUF_BYTES);

    const int tid  = threadIdx.x;
    const int lane = tid & 31;
    const int warp = tid >> 5;
    const int g = lane >> 2;
    const int t = lane & 3;
    const int qBase = blockIdx.x * 64;
    const int bh = blockIdx.y;
    const int b = bh >> 4;
    const int h = bh & 15;

    unsigned smem_base;
    {
        void* p = smc;
        asm("{ .reg .u64 tmp; cvta.to.shared.u64 tmp, %1; cvt.u32.u64 %0, tmp; }"
            : "=r"(smem_base) : "l"(p));
    }
    const unsigned ks_sm = smem_base;
    const unsigned vs_sm = smem_base + 2 * KBUF_BYTES;

    // mask -> smem, pre-scaled by log2e (scores live in log2 domain)
    #pragma unroll
    for (int i = 0; i < 4; i++) {
        const int idx = i * 128 + tid;
        float4 mv = ((const float4*)(mask + (size_t)b * S_))[idx];
        mv.x *= L2E; mv.y *= L2E; mv.z *= L2E; mv.w *= L2E;
        ((float4*)msk)[idx] = mv;
    }
    const float* Qp = g_Q + (size_t)bh * S_ * HD_;
    #pragma unroll
    for (int i = 0; i < 8; i++) {
        const int idx = i * 128 + tid;
        const int r = idx >> 4, c = idx & 15;
        *(float4*)&Qst[r * 68 + c * 4] = *(const float4*)&Qp[(size_t)(qBase + r) * HD_ + c * 4];
    }
    __syncthreads();

    unsigned qh[4][4], ql[4][4];
    const int qr = warp * 16 + g;
    #pragma unroll
    for (int kk = 0; kk < 4; kk++) {
        const int c0 = kk * 16 + 2 * t;
        float q00 = Qst[ qr      * 68 + c0], q01 = Qst[ qr      * 68 + c0 + 1];
        float q10 = Qst[(qr + 8) * 68 + c0], q11 = Qst[(qr + 8) * 68 + c0 + 1];
        float q02 = Qst[ qr      * 68 + c0 + 8], q03 = Qst[ qr      * 68 + c0 + 9];
        float q12 = Qst[(qr + 8) * 68 + c0 + 8], q13 = Qst[(qr + 8) * 68 + c0 + 9];
        float h00 = bfhi(q00), h01 = bfhi(q01), h10 = bfhi(q10), h11 = bfhi(q11);
        float h02 = bfhi(q02), h03 = bfhi(q03), h12 = bfhi(q12), h13 = bfhi(q13);
        qh[kk][0] = packbf(h00, h01);             qh[kk][1] = packbf(h10, h11);
        qh[kk][2] = packbf(h02, h03);             qh[kk][3] = packbf(h12, h13);
        ql[kk][0] = packbf(q00 - h00, q01 - h01); ql[kk][1] = packbf(q10 - h10, q11 - h11);
        ql[kk][2] = packbf(q02 - h02, q03 - h03); ql[kk][3] = packbf(q12 - h12, q13 - h13);
    }
    __syncthreads();

    const uint4*  gK = g_Kp + (size_t)bh * NT_ * 1024;
    const float4* gV = g_Vp + (size_t)bh * NT_ * 1024;

    #pragma unroll
    for (int i = 0; i < 8; i++) {
        const int idx = i * 128 + tid;
        const int fs = idx >> 6, r = idx & 63;
        cpa16(ks_sm + (fs * KSLD + r) * 16, gK + idx);
        cpa16(vs_sm + (fs * VSLD + r) * 16, gV + idx);
    }
    asm volatile("cp.async.commit_group;");

    float m_run0 = -CUDART_INF_F, m_run1 = -CUDART_INF_F;
    float l_run0 = 0.0f, l_run1 = 0.0f;
    float o[8][4];
    #pragma unroll
    for (int nt = 0; nt < 8; nt++)
        #pragma unroll
        for (int i = 0; i < 4; i++) o[nt][i] = 0.0f;

    const int bl  = lane & 28;
    const int sl0 = bl + (t >> 1);
    const int sl1 = sl0 + 2;
    const bool odd = (t & 1);

    int buf = 0;
    for (int kt = 0; kt < NT_; kt++) {
        if (kt + 1 < NT_) {
            const unsigned ksd = ks_sm + (buf ^ 1) * KBUF_BYTES;
            const unsigned vsd = vs_sm + (buf ^ 1) * VBUF_BYTES;
            const size_t tb = (size_t)(kt + 1) * 1024;
            #pragma unroll
            for (int i = 0; i < 8; i++) {
                const int idx = i * 128 + tid;
                const int fs = idx >> 6, r = idx & 63;
                cpa16(ksd + (fs * KSLD + r) * 16, gK + tb + idx);
                cpa16(vsd + (fs * VSLD + r) * 16, gV + tb + idx);
            }
            asm volatile("cp.async.commit_group;");
            asm volatile("cp.async.wait_group 1;");
        } else {
            asm volatile("cp.async.wait_group 0;");
        }
        __syncthreads();

        const uint4*  Kb = Ks + buf * (KBUF_BYTES / 16);
        const float4* Vb = Vs + buf * (VBUF_BYTES / 16);

        float s[8][4];
        #pragma unroll
        for (int nt = 0; nt < 8; nt++)
            #pragma unroll
            for (int i = 0; i < 4; i++) s[nt][i] = 0.0f;

        #pragma unroll
        for (int kk = 0; kk < 4; kk++) {
            #pragma unroll
            for (int nt = 0; nt < 8; nt++) {
                uint4 kb = Kb[(kk * 4 + t) * KSLD + nt * 8 + g];
                mma16(s[nt], qh[kk], kb.x, kb.y);
                mma16(s[nt], qh[kk], kb.z, kb.w);
                mma16(s[nt], ql[kk], kb.x, kb.y);
            }
        }

        // mask add (post-mma, overlaps tensor drain)
        const int kBase = kt * 64;
        #pragma unroll
        for (int nt = 0; nt < 8; nt++) {
            const int c = kBase + nt * 8 + 2 * t;
            const float mk0 = msk[c], mk1 = msk[c + 1];
            s[nt][0] += mk0; s[nt][1] += mk1;
            s[nt][2] += mk0; s[nt][3] += mk1;
        }

        float mx0 = -CUDART_INF_F, mx1 = -CUDART_INF_F;
        #pragma unroll
        for (int nt = 0; nt < 8; nt++) {
            mx0 = fmaxf(mx0, fmaxf(s[nt][0], s[nt][1]));
            mx1 = fmaxf(mx1, fmaxf(s[nt][2], s[nt][3]));
        }
        mx0 = fmaxf(mx0, __shfl_xor_sync(0xffffffffu, mx0, 1));
        mx0 = fmaxf(mx0, __shfl_xor_sync(0xffffffffu, mx0, 2));
        mx1 = fmaxf(mx1, __shfl_xor_sync(0xffffffffu, mx1, 1));
        mx1 = fmaxf(mx1, __shfl_xor_sync(0xffffffffu, mx1, 2));

        const float mn0 = fmaxf(m_run0, mx0);
        const float mn1 = fmaxf(m_run1, mx1);
        const float corr0 = ex2f(m_run0 - mn0);
        const float corr1 = ex2f(m_run1 - mn1);

        float sum0 = 0.0f, sum1 = 0.0f;
        #pragma unroll
        for (int nt = 0; nt < 8; nt++) {
            s[nt][0] = ex2f(s[nt][0] - mn0); sum0 += s[nt][0];
            s[nt][1] = ex2f(s[nt][1] - mn0); sum0 += s[nt][1];
            s[nt][2] = ex2f(s[nt][2] - mn1); sum1 += s[nt][2];
            s[nt][3] = ex2f(s[nt][3] - mn1); sum1 += s[nt][3];
        }
        sum0 += __shfl_xor_sync(0xffffffffu, sum0, 1);
        sum0 += __shfl_xor_sync(0xffffffffu, sum0, 2);
        sum1 += __shfl_xor_sync(0xffffffffu, sum1, 1);
        sum1 += __shfl_xor_sync(0xffffffffu, sum1, 2);

        l_run0 = l_run0 * corr0 + sum0;
        l_run1 = l_run1 * corr1 + sum1;
        m_run0 = mn0; m_run1 = mn1;

        #pragma unroll
        for (int nt = 0; nt < 8; nt++) {
            o[nt][0] *= corr0; o[nt][1] *= corr0;
            o[nt][2] *= corr1; o[nt][3] *= corr1;
        }

        // PV relayout: raw f32 bits as tf32 operands (HW truncates low bits)
        #pragma unroll
        for (int kk2 = 0; kk2 < 4; kk2++) {
            unsigned pa[2][4];
            #pragma unroll
            for (int half = 0; half < 2; half++) {
                float* ss = s[kk2 * 2 + half];
                float u0 = __shfl_sync(0xffffffffu, ss[0], sl0);
                float u1 = __shfl_sync(0xffffffffu, ss[1], sl0);
                float u2 = __shfl_sync(0xffffffffu, ss[2], sl0);
                float u3 = __shfl_sync(0xffffffffu, ss[3], sl0);
                float w0 = __shfl_sync(0xffffffffu, ss[0], sl1);
                float w1 = __shfl_sync(0xffffffffu, ss[1], sl1);
                float w2 = __shfl_sync(0xffffffffu, ss[2], sl1);
                float w3 = __shfl_sync(0xffffffffu, ss[3], sl1);
                pa[half][0] = __float_as_uint(odd ? u1 : u0);
                pa[half][1] = __float_as_uint(odd ? u3 : u2);
                pa[half][2] = __float_as_uint(odd ? w1 : w0);
                pa[half][3] = __float_as_uint(odd ? w3 : w2);
            }
            #pragma unroll
            for (int nt = 0; nt < 8; nt++) {
                float4 vv = Vb[(kk2 * 4 + t) * VSLD + nt * 8 + g];
                mma8(o[nt], pa[0], __float_as_uint(vv.x), __float_as_uint(vv.y));
                mma8(o[nt], pa[1], __float_as_uint(vv.z), __float_as_uint(vv.w));
            }
        }
        __syncthreads();
        buf ^= 1;
    }

    const float inv0 = 1.0f / l_run0;
    const float inv1 = 1.0f / l_run1;
    const int q0 = qBase + qr;
    #pragma unroll
    for (int nt = 0; nt < 8; nt++) {
        const int d = h * 64 + nt * 8 + 2 * t;
        float2 v0 = make_float2(o[nt][0] * inv0, o[nt][1] * inv0);
        float2 v1 = make_float2(o[nt][2] * inv1, o[nt][3] * inv1);
        *(float2*)&out[((size_t)(b * S_ + q0    )) * D_ + d] = v0;
        *(float2*)&out[((size_t)(b * S_ + q0 + 8)) * D_ + d] = v1;
    }
}

// ---------------------------------------------------------------------------
extern "C" void kernel_launch(void* const* d_in, const int* in_sizes, int n_in,
                              void* d_out, int out_size)
{
    const float* X    = (const float*)d_in[0];
    const float* mask = (const float*)d_in[1];
    const float* Wq   = (const float*)d_in[2];
    const float* bq   = (const float*)d_in[3];
    const float* Wk   = (const float*)d_in[4];
    const float* bk   = (const float*)d_in[5];
    const float* Wv   = (const float*)d_in[6];
    const float* bv   = (const float*)d_in[7];
    float* out = (float*)d_out;

    pack_in_kernel<<<2048 + 3072, 256>>>(X, Wq, Wk, Wv);
    {
        const int smem = QSTAGES * 16384;  // 64KB
        cudaFuncSetAttribute(qkv_kernel,
                             cudaFuncAttributeMaxDynamicSharedMemorySize, smem);
        dim3 grid(D_ / 128, (B_ * S_) / 128, 3);
        qkv_kernel<<<grid, 256, smem>>>(bq, bk, bv);
    }
    {
        const int smem = 2 * KBUF_BYTES + 2 * VBUF_BYTES + 2048 * 4;  // 75776
        cudaFuncSetAttribute(attn_kernel,
                             cudaFuncAttributeMaxDynamicSharedMemorySize, smem);
        dim3 grid(S_ / 64, B_ * H_);
        attn_kernel<<<grid, 128, smem>>>(mask, out);
    }
}

// round 16
// speedup vs baseline: 1.0135x; 1.0135x over previous
#include <cuda_runtime.h>
#include <cuda_bf16.h>
#include <math_constants.h>

#define B_  2
#define S_  2048
#define D_  1024
#define H_  16
#define HD_ 64
#define NT_ 32   // S_/64 attn k-tiles
#define KT_ 64   // D_/16 qkv k-tiles
#define L2E 1.4426950408889634f

// attention packed operands (written directly by qkv epilogue)
// Q a-frags: [bh][qt(32)][slot=warp*4+kk (16)][{hi:0-31, lo:32-63} by lane]
__device__ uint4  g_Qp[B_ * H_ * 32 * 16 * 64];
__device__ uint4  g_Kp[B_ * H_ * NT_ * 16 * 64];
__device__ float4 g_Vp[B_ * H_ * NT_ * 16 * 64];
// qkv packed inputs
__device__ uint4  g_Xp[KT_ * 256 * 2 * 32];
__device__ uint4  g_Wp[3 * KT_ * 1024 * 4];

__device__ __forceinline__ unsigned f2tf(float x) {
    unsigned r;
    asm("cvt.rna.tf32.f32 %0, %1;" : "=r"(r) : "f"(x));
    return r;
}
__device__ __forceinline__ float tf2f(unsigned u) { return __uint_as_float(u); }
__device__ __forceinline__ float tfr(float x) { return tf2f(f2tf(x)); }
__device__ __forceinline__ float bfhi(float x) {
    return __bfloat162float(__float2bfloat16_rn(x));
}
__device__ __forceinline__ unsigned packbf(float a, float b) {
    __nv_bfloat162 h = __floats2bfloat162_rn(a, b);
    return *(unsigned*)&h;
}
__device__ __forceinline__ float ex2f(float x) {
    float r;
    asm("ex2.approx.ftz.f32 %0, %1;" : "=f"(r) : "f"(x));
    return r;
}
__device__ __forceinline__ void mma8(float c[4], const unsigned a[4],
                                     unsigned b0, unsigned b1) {
    asm volatile(
        "mma.sync.aligned.m16n8k8.row.col.f32.tf32.tf32.f32 "
        "{%0,%1,%2,%3},{%4,%5,%6,%7},{%8,%9},{%0,%1,%2,%3};"
        : "+f"(c[0]), "+f"(c[1]), "+f"(c[2]), "+f"(c[3])
        : "r"(a[0]), "r"(a[1]), "r"(a[2]), "r"(a[3]), "r"(b0), "r"(b1));
}
__device__ __forceinline__ void mma16(float c[4], const unsigned a[4],
                                      unsigned b0, unsigned b1) {
    asm volatile(
        "mma.sync.aligned.m16n8k16.row.col.f32.bf16.bf16.f32 "
        "{%0,%1,%2,%3},{%4,%5,%6,%7},{%8,%9},{%0,%1,%2,%3};"
        : "+f"(c[0]), "+f"(c[1]), "+f"(c[2]), "+f"(c[3])
        : "r"(a[0]), "r"(a[1]), "r"(a[2]), "r"(a[3]), "r"(b0), "r"(b1));
}
__device__ __forceinline__ void cpa16(unsigned dst, const void* src) {
    asm volatile("cp.async.cg.shared.global [%0], [%1], 16;" :: "r"(dst), "l"(src));
}
__device__ __forceinline__ unsigned smem_u32(const void* p) {
    unsigned a;
    asm("{ .reg .u64 t; cvta.to.shared.u64 t, %1; cvt.u32.u64 %0, t; }"
        : "=r"(a) : "l"(p));
    return a;
}

// ---------------------------------------------------------------------------
// pack_in: X -> a-frags (blocks [0, 2048)), W -> b-frags (blocks [2048, 5120))
// ---------------------------------------------------------------------------
__global__ __launch_bounds__(256) void pack_in_kernel(
    const float* __restrict__ X,
    const float* __restrict__ Wq, const float* __restrict__ Wk, const float* __restrict__ Wv)
{
    if (blockIdx.x < 2048) {
        const int id = blockIdx.x * 256 + threadIdx.x;
        const int lane = id & 31;
        const int t = lane & 3, g = lane >> 2;
        const int mG = (id >> 5) & 255;
        const int kt = id >> 13;
        const int m  = mG * 16 + g;
        const int c0 = kt * 16 + 2 * t;

        float2 x00 = *(const float2*)&X[(size_t)m * D_ + c0];
        float2 x01 = *(const float2*)&X[(size_t)m * D_ + c0 + 8];
        float2 x10 = *(const float2*)&X[(size_t)(m + 8) * D_ + c0];
        float2 x11 = *(const float2*)&X[(size_t)(m + 8) * D_ + c0 + 8];

        float h00 = bfhi(x00.x), h01 = bfhi(x00.y);
        float h10 = bfhi(x10.x), h11 = bfhi(x10.y);
        float h02 = bfhi(x01.x), h03 = bfhi(x01.y);
        float h12 = bfhi(x11.x), h13 = bfhi(x11.y);

        uint4 hi, lo;
        hi.x = packbf(h00, h01);             hi.y = packbf(h10, h11);
        hi.z = packbf(h02, h03);             hi.w = packbf(h12, h13);
        lo.x = packbf(x00.x - h00, x00.y - h01);
        lo.y = packbf(x10.x - h10, x10.y - h11);
        lo.z = packbf(x01.x - h02, x01.y - h03);
        lo.w = packbf(x11.x - h12, x11.y - h13);

        const size_t base = ((size_t)kt * 256 + mG) * 64;
        g_Xp[base + lane]      = hi;
        g_Xp[base + 32 + lane] = lo;
    } else {
        const int id = (blockIdx.x - 2048) * 256 + threadIdx.x;
        const int t  = id & 3;
        const int n  = (id >> 2) & 1023;
        const int kt = (id >> 12) & 63;
        const int z  = id >> 18;
        const float* W = (z == 0) ? Wq : (z == 1) ? Wk : Wv;
        const int k0 = kt * 16;

        float w0 = W[(size_t)(k0 + 2*t    ) * D_ + n];
        float w1 = W[(size_t)(k0 + 2*t + 1) * D_ + n];
        float w2 = W[(size_t)(k0 + 2*t + 8) * D_ + n];
        float w3 = W[(size_t)(k0 + 2*t + 9) * D_ + n];
        float h0 = bfhi(w0), h1 = bfhi(w1), h2 = bfhi(w2), h3 = bfhi(w3);

        uint4 frag;
        frag.x = packbf(h0, h1);
        frag.y = packbf(h2, h3);
        frag.z = packbf(w0 - h0, w1 - h1);
        frag.w = packbf(w2 - h2, w3 - h3);
        g_Wp[id] = frag;
    }
}

// ---------------------------------------------------------------------------
// QKV projection: 4-stage cp.async pipeline (64KB), pure-copy mainloop.
// Epilogue: Q -> g_Qp a-frags; K -> g_Kp b-frags; V -> g_Vp frags (shuffled).
// ---------------------------------------------------------------------------
#define QSTAGES 4
__global__ __launch_bounds__(256) void qkv_kernel(
    const float* __restrict__ bq, const float* __restrict__ bk, const float* __restrict__ bv)
{
    const int z = blockIdx.z;
    const float* bias = (z == 0) ? bq : (z == 1) ? bk : bv;

    extern __shared__ uint4 sm[];
    const unsigned sm_base = smem_u32(sm);

    const int tid  = threadIdx.x;
    const int lane = tid & 31;
    const int warp = tid >> 5;
    const int wm = warp & 3;
    const int wn = warp >> 2;
    const int rowBase = blockIdx.y * 128;
    const int colBase = blockIdx.x * 128;
    const int g = lane >> 2;
    const int t = lane & 3;

    const uint4* gX = g_Xp + (size_t)(rowBase >> 4) * 64;
    const uint4* gW = g_Wp + (size_t)z * (KT_ * 4096) + colBase * 4;

    float acc[2][8][4];
    #pragma unroll
    for (int mt = 0; mt < 2; mt++)
        #pragma unroll
        for (int nt = 0; nt < 8; nt++)
            #pragma unroll
            for (int i = 0; i < 4; i++) acc[mt][nt][i] = 0.0f;

    #pragma unroll
    for (int st = 0; st < QSTAGES - 1; st++) {
        const unsigned dst = sm_base + st * 16384;
        #pragma unroll
        for (int i = 0; i < 4; i++) {
            const int j = i * 256 + tid;
            if (j < 512) cpa16(dst + j * 16, gX + (size_t)st * 16384 + j);
            else         cpa16(dst + j * 16, gW + (size_t)st * 4096 + (j - 512));
        }
        asm volatile("cp.async.commit_group;");
    }

    for (int kt = 0; kt < KT_; kt++) {
        if (kt + QSTAGES - 1 < KT_) {
            const int st = (kt + QSTAGES - 1) & (QSTAGES - 1);
            const unsigned dst = sm_base + st * 16384;
            const size_t xo = (size_t)(kt + QSTAGES - 1) * 16384;
            const size_t wo = (size_t)(kt + QSTAGES - 1) * 4096;
            #pragma unroll
            for (int i = 0; i < 4; i++) {
                const int j = i * 256 + tid;
                if (j < 512) cpa16(dst + j * 16, gX + xo + j);
                else         cpa16(dst + j * 16, gW + wo + (j - 512));
            }
        }
        asm volatile("cp.async.commit_group;");
        asm volatile("cp.async.wait_group %0;" :: "n"(QSTAGES - 1));
        __syncthreads();

        const uint4* As = sm + (kt & (QSTAGES - 1)) * 1024;
        const uint4* Bs = As + 512;

        unsigned ah[2][4], al[2][4];
        #pragma unroll
        for (int mt = 0; mt < 2; mt++) {
            uint4 h4 = As[(wm * 2 + mt) * 64 + lane];
            uint4 l4 = As[(wm * 2 + mt) * 64 + 32 + lane];
            ah[mt][0] = h4.x; ah[mt][1] = h4.y; ah[mt][2] = h4.z; ah[mt][3] = h4.w;
            al[mt][0] = l4.x; al[mt][1] = l4.y; al[mt][2] = l4.z; al[mt][3] = l4.w;
        }
        #pragma unroll
        for (int nt = 0; nt < 8; nt++) {
            uint4 bb = Bs[(wn * 64 + nt * 8 + g) * 4 + t];
            #pragma unroll
            for (int mt = 0; mt < 2; mt++) {
                mma16(acc[mt][nt], ah[mt], bb.x, bb.y);
                mma16(acc[mt][nt], ah[mt], bb.z, bb.w);
                mma16(acc[mt][nt], al[mt], bb.x, bb.y);
            }
        }
        __syncthreads();
    }

    const int hh = blockIdx.x * 2 + wn;   // head index for this warp's n-range

    if (z == 0) {
        // ---- Q: direct-pack bf16 hi/lo a-frags (attn layout), coalesced ----
        const float QSCALE = 0.125f * L2E;
        #pragma unroll
        for (int mt = 0; mt < 2; mt++) {
            const int m0 = rowBase + wm * 32 + mt * 16 + g;
            const int b0 = m0 >> 11;
            const int s0 = m0 & (S_ - 1);
            const int qt = s0 >> 6;
            const int wa = (s0 & 63) >> 4;
            const size_t base =
                (((size_t)(b0 * H_ + hh) * 32 + qt) * 16 + wa * 4) * 64 + lane;
            #pragma unroll
            for (int kk = 0; kk < 4; kk++) {
                const int n0 = colBase + wn * 64 + 16 * kk + 2 * t;
                const float b00 = bias[n0],     b01 = bias[n0 + 1];
                const float b08 = bias[n0 + 8], b09 = bias[n0 + 9];
                float a0 = (acc[mt][2*kk][0]   + b00) * QSCALE;
                float a1 = (acc[mt][2*kk][1]   + b01) * QSCALE;
                float a2 = (acc[mt][2*kk][2]   + b00) * QSCALE;
                float a3 = (acc[mt][2*kk][3]   + b01) * QSCALE;
                float a4 = (acc[mt][2*kk+1][0] + b08) * QSCALE;
                float a5 = (acc[mt][2*kk+1][1] + b09) * QSCALE;
                float a6 = (acc[mt][2*kk+1][2] + b08) * QSCALE;
                float a7 = (acc[mt][2*kk+1][3] + b09) * QSCALE;
                float h0 = bfhi(a0), h1 = bfhi(a1), h2 = bfhi(a2), h3 = bfhi(a3);
                float h4 = bfhi(a4), h5 = bfhi(a5), h6 = bfhi(a6), h7 = bfhi(a7);
                uint4 hv, lv;
                hv.x = packbf(h0, h1); hv.y = packbf(h2, h3);
                hv.z = packbf(h4, h5); hv.w = packbf(h6, h7);
                lv.x = packbf(a0 - h0, a1 - h1); lv.y = packbf(a2 - h2, a3 - h3);
                lv.z = packbf(a4 - h4, a5 - h5); lv.w = packbf(a6 - h6, a7 - h7);
                g_Qp[base + kk * 64]      = hv;
                g_Qp[base + kk * 64 + 32] = lv;
            }
        }
    } else if (z == 1) {
        // ---- K: direct-pack bf16 hi/lo uint4 frags, coalesced ----
        #pragma unroll
        for (int mt = 0; mt < 2; mt++) {
            const int m0 = rowBase + wm * 32 + mt * 16 + g;
            const int b0 = m0 >> 11;
            const int s0 = m0 & (S_ - 1);
            const int ktt = s0 >> 6, r64 = s0 & 63;
            const size_t base = (size_t)((b0 * H_ + hh) * NT_ + ktt) * 1024;
            #pragma unroll
            for (int j = 0; j < 4; j++) {
                const int n0 = colBase + wn * 64 + 16 * j + 2 * t;
                const float b00 = bias[n0],     b01 = bias[n0 + 1];
                const float b08 = bias[n0 + 8], b09 = bias[n0 + 9];
                float a0 = acc[mt][2*j][0] + b00, a1 = acc[mt][2*j][1] + b01;
                float a2 = acc[mt][2*j+1][0] + b08, a3 = acc[mt][2*j+1][1] + b09;
                float h0 = bfhi(a0), h1 = bfhi(a1), h2 = bfhi(a2), h3 = bfhi(a3);
                uint4 fr;
                fr.x = packbf(h0, h1);        fr.y = packbf(h2, h3);
                fr.z = packbf(a0 - h0, a1 - h1);
                fr.w = packbf(a2 - h2, a3 - h3);
                g_Kp[base + (size_t)(j * 4 + t) * 64 + r64] = fr;
                a0 = acc[mt][2*j][2] + b00; a1 = acc[mt][2*j][3] + b01;
                a2 = acc[mt][2*j+1][2] + b08; a3 = acc[mt][2*j+1][3] + b09;
                h0 = bfhi(a0); h1 = bfhi(a1); h2 = bfhi(a2); h3 = bfhi(a3);
                fr.x = packbf(h0, h1);        fr.y = packbf(h2, h3);
                fr.z = packbf(a0 - h0, a1 - h1);
                fr.w = packbf(a2 - h2, a3 - h3);
                g_Kp[base + (size_t)(j * 4 + t) * 64 + r64 + 8] = fr;
            }
        }
    } else {
        // ---- V: direct-pack transposed tf32 float4 frags via pair shuffles ----
        #pragma unroll
        for (int mt = 0; mt < 2; mt++) {
            const int m0 = rowBase + wm * 32 + mt * 16 + g;
            const int b0 = m0 >> 11;
            const int s0 = m0 & (S_ - 1);
            const int ktt = s0 >> 6;
            const int kk2 = (s0 >> 4) & 3;
            const int tpp = g & 3;
            const int gh  = g >> 2;
            const size_t base = ((size_t)((b0 * H_ + hh) * NT_ + ktt) * 16
                                 + kk2 * 4 + tpp) * 64;
            #pragma unroll
            for (int nt = 0; nt < 8; nt++) {
                const int n0 = colBase + wn * 64 + nt * 8 + 2 * t;
                const float bb0 = bias[n0], bb1 = bias[n0 + 1];
                float v0 = acc[mt][nt][0] + bb0;
                float v1 = acc[mt][nt][1] + bb1;
                float v2 = acc[mt][nt][2] + bb0;
                float v3 = acc[mt][nt][3] + bb1;
                float x0 = __shfl_xor_sync(0xffffffffu, v0, 16);
                float x1 = __shfl_xor_sync(0xffffffffu, v1, 16);
                float x2 = __shfl_xor_sync(0xffffffffu, v2, 16);
                float x3 = __shfl_xor_sync(0xffffffffu, v3, 16);
                float4 fr; int d;
                if (gh == 0) {
                    d = nt * 8 + 2 * t;
                    fr.x = tfr(v0); fr.y = tfr(x0); fr.z = tfr(v2); fr.w = tfr(x2);
                } else {
                    d = nt * 8 + 2 * t + 1;
                    fr.x = tfr(x1); fr.y = tfr(v1); fr.z = tfr(x3); fr.w = tfr(v3);
                }
                g_Vp[base + d] = fr;
            }
        }
    }
}

// ---------------------------------------------------------------------------
// Flash attention: ex2 softmax, post-mma mask, Q frags loaded pre-packed.
// 64-query blocks, 128 threads / 4 warps.
// ---------------------------------------------------------------------------
#define KSLD 66
#define VSLD 66
#define KBUF_BYTES (16 * KSLD * 16)
#define VBUF_BYTES (16 * VSLD * 16)
__global__ __launch_bounds__(128) void attn_kernel(
    const float* __restrict__ mask, float* __restrict__ out)
{
    extern __shared__ char smc[];
    uint4*  Ks   = (uint4*)smc;
    float4* Vs   = (float4*)(smc + 2 * KBUF_BYTES);
    float*  msk  = (float*)(smc + 2 * KBUF_BYTES + 2 * VBUF_BYTES);

    const int tid  = threadIdx.x;
    const int lane = tid & 31;
    const int warp = tid >> 5;
    const int g = lane >> 2;
    const int t = lane & 3;
    const int qBase = blockIdx.x * 64;
    const int bh = blockIdx.y;
    const int b = bh >> 4;
    const int h = bh & 15;

    const unsigned smem_base = smem_u32(smc);
    const unsigned ks_sm = smem_base;
    const unsigned vs_sm = smem_base + 2 * KBUF_BYTES;

    // mask -> smem, pre-scaled by log2e (first read is after in-loop barrier)
    #pragma unroll
    for (int i = 0; i < 4; i++) {
        const int idx = i * 128 + tid;
        float4 mv = ((const float4*)(mask + (size_t)b * S_))[idx];
        mv.x *= L2E; mv.y *= L2E; mv.z *= L2E; mv.w *= L2E;
        ((float4*)msk)[idx] = mv;
    }

    // Q frags: direct pre-packed loads (no smem staging, no conversion)
    unsigned qh[4][4], ql[4][4];
    {
        const uint4* gQ = g_Qp +
            (((size_t)bh * 32 + blockIdx.x) * 16 + warp * 4) * 64;
        #pragma unroll
        for (int kk = 0; kk < 4; kk++) {
            uint4 hv = gQ[kk * 64 + lane];
            uint4 lv = gQ[kk * 64 + 32 + lane];
            qh[kk][0] = hv.x; qh[kk][1] = hv.y; qh[kk][2] = hv.z; qh[kk][3] = hv.w;
            ql[kk][0] = lv.x; ql[kk][1] = lv.y; ql[kk][2] = lv.z; ql[kk][3] = lv.w;
        }
    }
    const int qr = warp * 16 + g;

    const uint4*  gK = g_Kp + (size_t)bh * NT_ * 1024;
    const float4* gV = g_Vp + (size_t)bh * NT_ * 1024;

    #pragma unroll
    for (int i = 0; i < 8; i++) {
        const int idx = i * 128 + tid;
        const int fs = idx >> 6, r = idx & 63;
        cpa16(ks_sm + (fs * KSLD + r) * 16, gK + idx);
        cpa16(vs_sm + (fs * VSLD + r) * 16, gV + idx);
    }
    asm volatile("cp.async.commit_group;");

    float m_run0 = -CUDART_INF_F, m_run1 = -CUDART_INF_F;
    float l_run0 = 0.0f, l_run1 = 0.0f;
    float o[8][4];
    #pragma unroll
    for (int nt = 0; nt < 8; nt++)
        #pragma unroll
        for (int i = 0; i < 4; i++) o[nt][i] = 0.0f;

    const int bl  = lane & 28;
    const int sl0 = bl + (t >> 1);
    const int sl1 = sl0 + 2;
    const bool odd = (t & 1);

    int buf = 0;
    for (int kt = 0; kt < NT_; kt++) {
        if (kt + 1 < NT_) {
            const unsigned ksd = ks_sm + (buf ^ 1) * KBUF_BYTES;
            const unsigned vsd = vs_sm + (buf ^ 1) * VBUF_BYTES;
            const size_t tb = (size_t)(kt + 1) * 1024;
            #pragma unroll
            for (int i = 0; i < 8; i++) {
                const int idx = i * 128 + tid;
                const int fs = idx >> 6, r = idx & 63;
                cpa16(ksd + (fs * KSLD + r) * 16, gK + tb + idx);
                cpa16(vsd + (fs * VSLD + r) * 16, gV + tb + idx);
            }
            asm volatile("cp.async.commit_group;");
            asm volatile("cp.async.wait_group 1;");
        } else {
            asm volatile("cp.async.wait_group 0;");
        }
        __syncthreads();

        const uint4*  Kb = Ks + buf * (KBUF_BYTES / 16);
        const float4* Vb = Vs + buf * (VBUF_BYTES / 16);

        float s[8][4];
        #pragma unroll
        for (int nt = 0; nt < 8; nt++)
            #pragma unroll
            for (int i = 0; i < 4; i++) s[nt][i] = 0.0f;

        #pragma unroll
        for (int kk = 0; kk < 4; kk++) {
            #pragma unroll
            for (int nt = 0; nt < 8; nt++) {
                uint4 kb = Kb[(kk * 4 + t) * KSLD + nt * 8 + g];
                mma16(s[nt], qh[kk], kb.x, kb.y);
                mma16(s[nt], qh[kk], kb.z, kb.w);
                mma16(s[nt], ql[kk], kb.x, kb.y);
            }
        }

        // mask add (post-mma, overlaps tensor drain)
        const int kBase = kt * 64;
        #pragma unroll
        for (int nt = 0; nt < 8; nt++) {
            const int c = kBase + nt * 8 + 2 * t;
            const float mk0 = msk[c], mk1 = msk[c + 1];
            s[nt][0] += mk0; s[nt][1] += mk1;
            s[nt][2] += mk0; s[nt][3] += mk1;
        }

        float mx0 = -CUDART_INF_F, mx1 = -CUDART_INF_F;
        #pragma unroll
        for (int nt = 0; nt < 8; nt++) {
            mx0 = fmaxf(mx0, fmaxf(s[nt][0], s[nt][1]));
            mx1 = fmaxf(mx1, fmaxf(s[nt][2], s[nt][3]));
        }
        mx0 = fmaxf(mx0, __shfl_xor_sync(0xffffffffu, mx0, 1));
        mx0 = fmaxf(mx0, __shfl_xor_sync(0xffffffffu, mx0, 2));
        mx1 = fmaxf(mx1, __shfl_xor_sync(0xffffffffu, mx1, 1));
        mx1 = fmaxf(mx1, __shfl_xor_sync(0xffffffffu, mx1, 2));

        const float mn0 = fmaxf(m_run0, mx0);
        const float mn1 = fmaxf(m_run1, mx1);
        const float corr0 = ex2f(m_run0 - mn0);
        const float corr1 = ex2f(m_run1 - mn1);

        float sum0 = 0.0f, sum1 = 0.0f;
        #pragma unroll
        for (int nt = 0; nt < 8; nt++) {
            s[nt][0] = ex2f(s[nt][0] - mn0); sum0 += s[nt][0];
            s[nt][1] = ex2f(s[nt][1] - mn0); sum0 += s[nt][1];
            s[nt][2] = ex2f(s[nt][2] - mn1); sum1 += s[nt][2];
            s[nt][3] = ex2f(s[nt][3] - mn1); sum1 += s[nt][3];
        }
        sum0 += __shfl_xor_sync(0xffffffffu, sum0, 1);
        sum0 += __shfl_xor_sync(0xffffffffu, sum0, 2);
        sum1 += __shfl_xor_sync(0xffffffffu, sum1, 1);
        sum1 += __shfl_xor_sync(0xffffffffu, sum1, 2);

        l_run0 = l_run0 * corr0 + sum0;
        l_run1 = l_run1 * corr1 + sum1;
        m_run0 = mn0; m_run1 = mn1;

        #pragma unroll
        for (int nt = 0; nt < 8; nt++) {
            o[nt][0] *= corr0; o[nt][1] *= corr0;
            o[nt][2] *= corr1; o[nt][3] *= corr1;
        }

        #pragma unroll
        for (int kk2 = 0; kk2 < 4; kk2++) {
            unsigned pa[2][4];
            #pragma unroll
            for (int half = 0; half < 2; half++) {
                float* ss = s[kk2 * 2 + half];
                float u0 = __shfl_sync(0xffffffffu, ss[0], sl0);
                float u1 = __shfl_sync(0xffffffffu, ss[1], sl0);
                float u2 = __shfl_sync(0xffffffffu, ss[2], sl0);
                float u3 = __shfl_sync(0xffffffffu, ss[3], sl0);
                float w0 = __shfl_sync(0xffffffffu, ss[0], sl1);
                float w1 = __shfl_sync(0xffffffffu, ss[1], sl1);
                float w2 = __shfl_sync(0xffffffffu, ss[2], sl1);
                float w3 = __shfl_sync(0xffffffffu, ss[3], sl1);
                pa[half][0] = f2tf(odd ? u1 : u0);
                pa[half][1] = f2tf(odd ? u3 : u2);
                pa[half][2] = f2tf(odd ? w1 : w0);
                pa[half][3] = f2tf(odd ? w3 : w2);
            }
            #pragma unroll
            for (int nt = 0; nt < 8; nt++) {
                float4 vv = Vb[(kk2 * 4 + t) * VSLD + nt * 8 + g];
                mma8(o[nt], pa[0], __float_as_uint(vv.x), __float_as_uint(vv.y));
                mma8(o[nt], pa[1], __float_as_uint(vv.z), __float_as_uint(vv.w));
            }
        }
        __syncthreads();
        buf ^= 1;
    }

    const float inv0 = 1.0f / l_run0;
    const float inv1 = 1.0f / l_run1;
    const int q0 = qBase + qr;
    #pragma unroll
    for (int nt = 0; nt < 8; nt++) {
        const int d = h * 64 + nt * 8 + 2 * t;
        float2 v0 = make_float2(o[nt][0] * inv0, o[nt][1] * inv0);
        float2 v1 = make_float2(o[nt][2] * inv1, o[nt][3] * inv1);
        *(float2*)&out[((size_t)(b * S_ + q0    )) * D_ + d] = v0;
        *(float2*)&out[((size_t)(b * S_ + q0 + 8)) * D_ + d] = v1;
    }
}

// ---------------------------------------------------------------------------
extern "C" void kernel_launch(void* const* d_in, const int* in_sizes, int n_in,
                              void* d_out, int out_size)
{
    const float* X    = (const float*)d_in[0];
    const float* mask = (const float*)d_in[1];
    const float* Wq   = (const float*)d_in[2];
    const float* bq   = (const float*)d_in[3];
    const float* Wk   = (const float*)d_in[4];
    const float* bk   = (const float*)d_in[5];
    const float* Wv   = (const float*)d_in[6];
    const float* bv   = (const float*)d_in[7];
    float* out = (float*)d_out;

    pack_in_kernel<<<2048 + 3072, 256>>>(X, Wq, Wk, Wv);
    {
        const int smem = QSTAGES * 16384;  // 64KB
        cudaFuncSetAttribute(qkv_kernel,
                             cudaFuncAttributeMaxDynamicSharedMemorySize, smem);
        dim3 grid(D_ / 128, (B_ * S_) / 128, 3);
        qkv_kernel<<<grid, 256, smem>>>(bq, bk, bv);
    }
    {
        const int smem = 2 * KBUF_BYTES + 2 * VBUF_BYTES + 2048 * 4;  // 75776
        cudaFuncSetAttribute(attn_kernel,
                             cudaFuncAttributeMaxDynamicSharedMemorySize, smem);
        dim3 grid(S_ / 64, B_ * H_);
        attn_kernel<<<grid, 128, smem>>>(mask, out);
    }
}